// round 6
// baseline (speedup 1.0000x reference)
#include <cuda_runtime.h>
#include <math.h>
#include <stdint.h>

#define T_STEPS 2048
#define BATCH   32
#define HID     256
#define ZCOLS   1024            // 4*HID, gate order f,i,o,c
#define MROWS   (T_STEPS * BATCH)
#define CLUSTER 8
#define REC_CTAS 128            // 16 clusters x 8 CTAs
#define REC_THREADS 256

// ---------------- scratch (device globals: no allocations allowed) ----------
__device__ float g_Zx[(size_t)MROWS * ZCOLS];   // row-major: Zx[t*32+b][col]

// ============================================================================
// Kernel 1: Zx[t*32+b][g*256+j] = sum_k x[b][t][k] * Wg[k][j] + bg[j]
// 128x128 tile SGEMM, BK=16, 256 threads, 8x8 microtile.
// ============================================================================
__global__ __launch_bounds__(256, 2)
void gemm_zx(const float* __restrict__ x,
             const float* __restrict__ Wf, const float* __restrict__ bf,
             const float* __restrict__ Wi, const float* __restrict__ bi,
             const float* __restrict__ Wo, const float* __restrict__ bo,
             const float* __restrict__ Wc, const float* __restrict__ bc)
{
    __shared__ float As[16 * 128];   // [k][m]
    __shared__ float Bs[16 * 128];   // [k][n]

    const int t = threadIdx.x;

    const float* Wg[4] = {Wf, Wi, Wo, Wc};
    const float* bg[4] = {bf, bi, bo, bc};

    const int N0 = blockIdx.x * 128;          // never straddles a gate
    const int gate = N0 >> 8;
    const int jb = N0 & 255;
    const float* __restrict__ W = Wg[gate];

    const int M0 = blockIdx.y * 128;
    const int tx = t & 15;
    const int ty = t >> 4;

    float acc[8][8];
    #pragma unroll
    for (int i = 0; i < 8; i++)
        #pragma unroll
        for (int j = 0; j < 8; j++) acc[i][j] = 0.f;

    for (int k0 = 0; k0 < 256; k0 += 16) {
        #pragma unroll
        for (int i = 0; i < 2; i++) {
            int f = t + i * 256;
            int kq  = f >> 7;
            int row = f & 127;
            int m   = M0 + row;
            int bb  = m & 31;
            int tt  = m >> 5;
            float4 a = *reinterpret_cast<const float4*>(
                x + ((size_t)bb * T_STEPS + tt) * 256 + k0 + kq * 4);
            As[(kq * 4 + 0) * 128 + row] = a.x;
            As[(kq * 4 + 1) * 128 + row] = a.y;
            As[(kq * 4 + 2) * 128 + row] = a.z;
            As[(kq * 4 + 3) * 128 + row] = a.w;
            int kk = f >> 5;
            int nq = f & 31;
            *reinterpret_cast<float4*>(&Bs[kk * 128 + nq * 4]) =
                *reinterpret_cast<const float4*>(W + (size_t)(k0 + kk) * 256 + jb + nq * 4);
        }
        __syncthreads();

        #pragma unroll
        for (int k = 0; k < 16; k++) {
            float a[8], bv[8];
            *reinterpret_cast<float4*>(&a[0])  = *reinterpret_cast<float4*>(&As[k * 128 + ty * 8]);
            *reinterpret_cast<float4*>(&a[4])  = *reinterpret_cast<float4*>(&As[k * 128 + ty * 8 + 4]);
            *reinterpret_cast<float4*>(&bv[0]) = *reinterpret_cast<float4*>(&Bs[k * 128 + tx * 8]);
            *reinterpret_cast<float4*>(&bv[4]) = *reinterpret_cast<float4*>(&Bs[k * 128 + tx * 8 + 4]);
            #pragma unroll
            for (int i = 0; i < 8; i++)
                #pragma unroll
                for (int j = 0; j < 8; j++)
                    acc[i][j] = fmaf(a[i], bv[j], acc[i][j]);
        }
        __syncthreads();
    }

    const float* __restrict__ bias = bg[gate];
    #pragma unroll
    for (int i = 0; i < 8; i++) {
        int m = M0 + ty * 8 + i;
        float* zr = g_Zx + (size_t)m * ZCOLS + N0 + tx * 8;
        float4 v0, v1;
        v0.x = acc[i][0] + bias[jb + tx * 8 + 0];
        v0.y = acc[i][1] + bias[jb + tx * 8 + 1];
        v0.z = acc[i][2] + bias[jb + tx * 8 + 2];
        v0.w = acc[i][3] + bias[jb + tx * 8 + 3];
        v1.x = acc[i][4] + bias[jb + tx * 8 + 4];
        v1.y = acc[i][5] + bias[jb + tx * 8 + 5];
        v1.z = acc[i][6] + bias[jb + tx * 8 + 6];
        v1.w = acc[i][7] + bias[jb + tx * 8 + 7];
        *reinterpret_cast<float4*>(zr)     = v0;
        *reinterpret_cast<float4*>(zr + 4) = v1;
    }
}

// ============================================================================
// Kernel 2: cluster recurrence. 16 clusters x 8 CTAs; cluster = 2 batches.
// CTA rank r owns hidden units [32r, 32r+32) for ALL 4 gates -> c,h local.
// Exchange: 64 (b,u) threads push their hv scalar to 7 peers (DSMEM store),
// then a full barrier.cluster (release/acquire) per step - the pattern the
// validated 2CTA examples use for peer-SMEM visibility.
// ============================================================================
__device__ __forceinline__ uint32_t smem_u32(const void* p) {
    uint32_t a;
    asm("{ .reg .u64 t; cvta.to.shared.u64 t, %1; cvt.u32.u64 %0, t; }"
        : "=r"(a) : "l"(p));
    return a;
}

#define SW_FLOATS   (256 * 128)          // weights [k][pc], pc = gate*32 + ul
#define SH_FLOATS   (2 * 2 * 256)        // h [buf][b][k]
#define SP_FLOATS   (8 * 2 * 128)        // partials [ks][b][pc]
#define SG_FLOATS   (4 * 2 * 32)         // gates [g][b][ul]
#define SC_FLOATS   (2 * 32)             // cell state [b][ul]
#define SMEM_FLOATS (SW_FLOATS + SH_FLOATS + SP_FLOATS + SG_FLOATS + SC_FLOATS)
#define SMEM_BYTES  (SMEM_FLOATS * 4)

__global__ __launch_bounds__(REC_THREADS, 1) __cluster_dims__(CLUSTER, 1, 1)
void lstm_rec(const float* __restrict__ Wf, const float* __restrict__ Wi,
              const float* __restrict__ Wo, const float* __restrict__ Wc,
              float* __restrict__ out)
{
    extern __shared__ float smem[];
    float* s_W    = smem;                     // [256][128]
    float* s_h    = s_W + SW_FLOATS;          // [2][2][256]
    float* s_part = s_h + SH_FLOATS;          // [8][2][128]
    float* s_gate = s_part + SP_FLOATS;       // [4][2][32]
    float* s_c    = s_gate + SG_FLOATS;       // [2][32]

    const int tid  = threadIdx.x;
    const int rank = blockIdx.x & (CLUSTER - 1);
    const int cid  = blockIdx.x >> 3;         // cluster id 0..15
    const int bb0  = cid * 2;                 // global batches bb0, bb0+1
    const float* Wg[4] = {Wf, Wi, Wo, Wc};

    const uint32_t smem_base = smem_u32(smem);

    // stage weights: s_W[k][pc] = Wg[pc>>5][(256+k)*256 + rank*32 + (pc&31)]
    for (int idx = tid; idx < SW_FLOATS; idx += REC_THREADS) {
        int k = idx >> 7, pc = idx & 127;
        s_W[idx] = Wg[pc >> 5][(size_t)(256 + k) * 256 + rank * 32 + (pc & 31)];
    }
    for (int i = tid; i < SH_FLOATS; i += REC_THREADS) s_h[i] = 0.f;
    if (tid < 64) s_c[tid] = 0.f;

    // combine / update roles
    const int cb  = tid >> 7;                 // batch for combine
    const int col = tid & 127;                // z-col 0..127 (pc)
    const int gate = col >> 5, ul = col & 31;
    const size_t zx_col = (size_t)gate * 256 + rank * 32 + ul;

    // GEMV roles: warp ks (k-range of 32), lane colq (4 cols), both batches
    const int ks   = tid >> 5;
    const int colq = tid & 31;

    // prefetch Zx(0)
    float pf = __ldcg(g_Zx + ((size_t)0 * 32 + bb0 + cb) * ZCOLS + zx_col);

    __syncthreads();
    asm volatile("barrier.cluster.arrive.aligned;" ::: "memory");
    asm volatile("barrier.cluster.wait.aligned;" ::: "memory");

    for (int t = 0; t < T_STEPS; t++) {
        const int cbuf = t & 1, nbuf = cbuf ^ 1;

        // prefetch Zx(t+1) early (lands during GEMV)
        float pf_next = 0.f;
        if (t + 1 < T_STEPS)
            pf_next = __ldcg(g_Zx + ((size_t)(t + 1) * 32 + bb0 + cb) * ZCOLS + zx_col);

        // GEMV partial: 4 cols x 2 batches x 32 k per thread.
        // Weight float4 reused across both batches -> crossbar == FMA floor.
        {
            const float* hb0 = s_h + (cbuf * 2) * 256 + ks * 32;
            const float* hb1 = hb0 + 256;
            const float* wk  = s_W + (ks * 32) * 128 + colq * 4;
            float4 A0 = make_float4(0.f, 0.f, 0.f, 0.f), A1 = A0;
            #pragma unroll
            for (int j = 0; j < 8; j++) {
                float4 h0 = *reinterpret_cast<const float4*>(hb0 + j * 4);
                float4 h1 = *reinterpret_cast<const float4*>(hb1 + j * 4);
                float4 w;
                w = *reinterpret_cast<const float4*>(wk + (j * 4 + 0) * 128);
                A0.x = fmaf(w.x, h0.x, A0.x); A0.y = fmaf(w.y, h0.x, A0.y);
                A0.z = fmaf(w.z, h0.x, A0.z); A0.w = fmaf(w.w, h0.x, A0.w);
                A1.x = fmaf(w.x, h1.x, A1.x); A1.y = fmaf(w.y, h1.x, A1.y);
                A1.z = fmaf(w.z, h1.x, A1.z); A1.w = fmaf(w.w, h1.x, A1.w);
                w = *reinterpret_cast<const float4*>(wk + (j * 4 + 1) * 128);
                A0.x = fmaf(w.x, h0.y, A0.x); A0.y = fmaf(w.y, h0.y, A0.y);
                A0.z = fmaf(w.z, h0.y, A0.z); A0.w = fmaf(w.w, h0.y, A0.w);
                A1.x = fmaf(w.x, h1.y, A1.x); A1.y = fmaf(w.y, h1.y, A1.y);
                A1.z = fmaf(w.z, h1.y, A1.z); A1.w = fmaf(w.w, h1.y, A1.w);
                w = *reinterpret_cast<const float4*>(wk + (j * 4 + 2) * 128);
                A0.x = fmaf(w.x, h0.z, A0.x); A0.y = fmaf(w.y, h0.z, A0.y);
                A0.z = fmaf(w.z, h0.z, A0.z); A0.w = fmaf(w.w, h0.z, A0.w);
                A1.x = fmaf(w.x, h1.z, A1.x); A1.y = fmaf(w.y, h1.z, A1.y);
                A1.z = fmaf(w.z, h1.z, A1.z); A1.w = fmaf(w.w, h1.z, A1.w);
                w = *reinterpret_cast<const float4*>(wk + (j * 4 + 3) * 128);
                A0.x = fmaf(w.x, h0.w, A0.x); A0.y = fmaf(w.y, h0.w, A0.y);
                A0.z = fmaf(w.z, h0.w, A0.z); A0.w = fmaf(w.w, h0.w, A0.w);
                A1.x = fmaf(w.x, h1.w, A1.x); A1.y = fmaf(w.y, h1.w, A1.y);
                A1.z = fmaf(w.z, h1.w, A1.z); A1.w = fmaf(w.w, h1.w, A1.w);
            }
            *reinterpret_cast<float4*>(s_part + (ks * 2 + 0) * 128 + colq * 4) = A0;
            *reinterpret_cast<float4*>(s_part + (ks * 2 + 1) * 128 + colq * 4) = A1;
        }
        __syncthreads();

        // combine partials + Zx, apply nonlinearity
        {
            float z = pf;
            #pragma unroll
            for (int q = 0; q < 8; q++)
                z += s_part[(q * 2 + cb) * 128 + col];
            float v = (gate < 3) ? (1.f / (1.f + __expf(-z))) : tanhf(z);
            s_gate[(gate * 2 + cb) * 32 + ul] = v;
        }
        pf = pf_next;
        __syncthreads();

        // c,h update (all 4 gates local) + local write + push to 7 peers
        if (tid < 64) {
            int b = tid >> 5, u = tid & 31;
            float fg = s_gate[(0 * 2 + b) * 32 + u];
            float ig = s_gate[(1 * 2 + b) * 32 + u];
            float og = s_gate[(2 * 2 + b) * 32 + u];
            float gg = s_gate[(3 * 2 + b) * 32 + u];
            float cv = fmaf(fg, s_c[tid], ig * gg);
            s_c[tid] = cv;
            float hv = og * tanhf(cv);
            int hoff = (nbuf * 2 + b) * 256 + rank * 32 + u;
            s_h[hoff] = hv;
            out[((size_t)(bb0 + b) * T_STEPS + (T_STEPS - 1 - t)) * HID
                + rank * 32 + u] = hv;

            if (t + 1 < T_STEPS) {
                uint32_t laddr = smem_base + (uint32_t)((SW_FLOATS + hoff) * 4);
                uint32_t hbits = __float_as_uint(hv);
                #pragma unroll
                for (int p = 0; p < CLUSTER; p++) {
                    if (p != rank) {
                        asm volatile(
                            "{\n\t.reg .b32 ra;\n\t"
                            "mapa.shared::cluster.u32 ra, %0, %1;\n\t"
                            "st.shared::cluster.b32 [ra], %2;\n\t}"
                            :: "r"(laddr), "r"(p), "r"(hbits) : "memory");
                    }
                }
            }
        }

        // cluster-wide barrier: release our pushes, acquire peers' pushes
        if (t + 1 < T_STEPS) {
            asm volatile("barrier.cluster.arrive.aligned;" ::: "memory");
            asm volatile("barrier.cluster.wait.aligned;" ::: "memory");
        }
    }

    // no remote ops in flight after last step (no push at t = T-1), but sync
    // before exit per DSMEM discipline
    asm volatile("barrier.cluster.arrive.aligned;" ::: "memory");
    asm volatile("barrier.cluster.wait.aligned;" ::: "memory");
}

// ============================================================================
extern "C" void kernel_launch(void* const* d_in, const int* in_sizes, int n_in,
                              void* d_out, int out_size)
{
    const float* x  = (const float*)d_in[0];
    const float* Wf = (const float*)d_in[1];
    const float* bf = (const float*)d_in[2];
    const float* Wi = (const float*)d_in[3];
    const float* bi = (const float*)d_in[4];
    const float* Wo = (const float*)d_in[5];
    const float* bo = (const float*)d_in[6];
    const float* Wc = (const float*)d_in[7];
    const float* bc = (const float*)d_in[8];
    float* out = (float*)d_out;

    cudaFuncSetAttribute(lstm_rec,
                         cudaFuncAttributeMaxDynamicSharedMemorySize, SMEM_BYTES);

    dim3 g1(ZCOLS / 128, MROWS / 128);   // 8 x 512
    gemm_zx<<<g1, 256>>>(x, Wf, bf, Wi, bi, Wo, bo, Wc, bc);
    lstm_rec<<<REC_CTAS, REC_THREADS, SMEM_BYTES>>>(Wf, Wi, Wo, Wc, out);
}

// round 7
// speedup vs baseline: 1.3705x; 1.3705x over previous
#include <cuda_runtime.h>
#include <math.h>
#include <stdint.h>

#define T_STEPS 2048
#define BATCH   32
#define HID     256
#define ZCOLS   1024            // 4*HID, gate order f,i,o,c
#define MROWS   (T_STEPS * BATCH)
#define CLUSTER 8
#define REC_CTAS 128            // 16 clusters x 8 CTAs
#define REC_THREADS 256

// ---------------- scratch (device globals: no allocations allowed) ----------
__device__ float g_Zx[(size_t)MROWS * ZCOLS];   // row-major: Zx[t*32+b][col]

// ============================================================================
// Kernel 1: Zx[t*32+b][g*256+j] = sum_k x[b][t][k] * Wg[k][j] + bg[j]
// 128x128 tile SGEMM, BK=16, 256 threads, 8x8 microtile.
// ============================================================================
__global__ __launch_bounds__(256, 2)
void gemm_zx(const float* __restrict__ x,
             const float* __restrict__ Wf, const float* __restrict__ bf,
             const float* __restrict__ Wi, const float* __restrict__ bi,
             const float* __restrict__ Wo, const float* __restrict__ bo,
             const float* __restrict__ Wc, const float* __restrict__ bc)
{
    __shared__ float As[16 * 128];   // [k][m]
    __shared__ float Bs[16 * 128];   // [k][n]

    const int t = threadIdx.x;

    const float* Wg[4] = {Wf, Wi, Wo, Wc};
    const float* bg[4] = {bf, bi, bo, bc};

    const int N0 = blockIdx.x * 128;          // never straddles a gate
    const int gate = N0 >> 8;
    const int jb = N0 & 255;
    const float* __restrict__ W = Wg[gate];

    const int M0 = blockIdx.y * 128;
    const int tx = t & 15;
    const int ty = t >> 4;

    float acc[8][8];
    #pragma unroll
    for (int i = 0; i < 8; i++)
        #pragma unroll
        for (int j = 0; j < 8; j++) acc[i][j] = 0.f;

    for (int k0 = 0; k0 < 256; k0 += 16) {
        #pragma unroll
        for (int i = 0; i < 2; i++) {
            int f = t + i * 256;
            int kq  = f >> 7;
            int row = f & 127;
            int m   = M0 + row;
            int bb  = m & 31;
            int tt  = m >> 5;
            float4 a = *reinterpret_cast<const float4*>(
                x + ((size_t)bb * T_STEPS + tt) * 256 + k0 + kq * 4);
            As[(kq * 4 + 0) * 128 + row] = a.x;
            As[(kq * 4 + 1) * 128 + row] = a.y;
            As[(kq * 4 + 2) * 128 + row] = a.z;
            As[(kq * 4 + 3) * 128 + row] = a.w;
            int kk = f >> 5;
            int nq = f & 31;
            *reinterpret_cast<float4*>(&Bs[kk * 128 + nq * 4]) =
                *reinterpret_cast<const float4*>(W + (size_t)(k0 + kk) * 256 + jb + nq * 4);
        }
        __syncthreads();

        #pragma unroll
        for (int k = 0; k < 16; k++) {
            float a[8], bv[8];
            *reinterpret_cast<float4*>(&a[0])  = *reinterpret_cast<float4*>(&As[k * 128 + ty * 8]);
            *reinterpret_cast<float4*>(&a[4])  = *reinterpret_cast<float4*>(&As[k * 128 + ty * 8 + 4]);
            *reinterpret_cast<float4*>(&bv[0]) = *reinterpret_cast<float4*>(&Bs[k * 128 + tx * 8]);
            *reinterpret_cast<float4*>(&bv[4]) = *reinterpret_cast<float4*>(&Bs[k * 128 + tx * 8 + 4]);
            #pragma unroll
            for (int i = 0; i < 8; i++)
                #pragma unroll
                for (int j = 0; j < 8; j++)
                    acc[i][j] = fmaf(a[i], bv[j], acc[i][j]);
        }
        __syncthreads();
    }

    const float* __restrict__ bias = bg[gate];
    #pragma unroll
    for (int i = 0; i < 8; i++) {
        int m = M0 + ty * 8 + i;
        float* zr = g_Zx + (size_t)m * ZCOLS + N0 + tx * 8;
        float4 v0, v1;
        v0.x = acc[i][0] + bias[jb + tx * 8 + 0];
        v0.y = acc[i][1] + bias[jb + tx * 8 + 1];
        v0.z = acc[i][2] + bias[jb + tx * 8 + 2];
        v0.w = acc[i][3] + bias[jb + tx * 8 + 3];
        v1.x = acc[i][4] + bias[jb + tx * 8 + 4];
        v1.y = acc[i][5] + bias[jb + tx * 8 + 5];
        v1.z = acc[i][6] + bias[jb + tx * 8 + 6];
        v1.w = acc[i][7] + bias[jb + tx * 8 + 7];
        *reinterpret_cast<float4*>(zr)     = v0;
        *reinterpret_cast<float4*>(zr + 4) = v1;
    }
}

// ============================================================================
// Kernel 2: cluster recurrence with st.async + mbarrier tx-counting exchange.
// 16 clusters x 8 CTAs; cluster = 2 batches; CTA owns 32 units x 4 gates.
// Boundary t (after step t): all ranks st.async their h-slice (8B x 32 jobs)
// into every rank's s_h (incl self); completion = 2048B tx on bar[t&1].
// ============================================================================
__device__ __forceinline__ uint32_t smem_u32(const void* p) {
    uint32_t a;
    asm("{ .reg .u64 t; cvta.to.shared.u64 t, %1; cvt.u32.u64 %0, t; }"
        : "=r"(a) : "l"(p));
    return a;
}

__device__ __forceinline__ float fast_sigmoid(float z) {
    return __fdividef(1.f, 1.f + __expf(-z));
}
__device__ __forceinline__ float fast_tanh(float z) {
    // 1 - 2/(e^{2z}+1); exact at +-inf, err ~1e-6
    return 1.f - __fdividef(2.f, __expf(2.f * z) + 1.f);
}

// smem layout (floats), after the 2 mbarriers (16 bytes)
#define SW_FLOATS   (256 * 128)          // weights [k][pc], pc = gate*32 + ul
#define SH_FLOATS   (2 * 2 * 256)        // h [buf][b][k]  (written by st.async)
#define SP_FLOATS   (8 * 2 * 128)        // partials [ks][b][pc]
#define SST_FLOATS  64                   // h staging [b][u]
#define SC_FLOATS   (2 * 32)             // cell state [b][u]
#define SMEM_FLOATS (SW_FLOATS + SH_FLOATS + SP_FLOATS + SST_FLOATS + SC_FLOATS)
#define SMEM_BYTES  (16 + SMEM_FLOATS * 4)
#define INBOX_TX    2048                 // 8 ranks x 256B per boundary

__global__ __launch_bounds__(REC_THREADS, 1) __cluster_dims__(CLUSTER, 1, 1)
void lstm_rec(const float* __restrict__ Wf, const float* __restrict__ Wi,
              const float* __restrict__ Wo, const float* __restrict__ Wc,
              float* __restrict__ out)
{
    extern __shared__ float smem_raw[];
    // [0..15]: bar0, bar1
    float* s_W     = smem_raw + 4;            // [256][128]
    float* s_h     = s_W + SW_FLOATS;         // [2][2][256]
    float* s_part  = s_h + SH_FLOATS;         // [8][2][128]
    float* s_stage = s_part + SP_FLOATS;      // [2][32]
    float* s_c     = s_stage + SST_FLOATS;    // [2][32]

    const int tid  = threadIdx.x;
    const int rank = blockIdx.x & (CLUSTER - 1);
    const int cid  = blockIdx.x >> 3;
    const int bb0  = cid * 2;
    const float* Wg[4] = {Wf, Wi, Wo, Wc};

    const uint32_t smem_base = smem_u32(smem_raw);
    const uint32_t bar0 = smem_base;
    const uint32_t bar1 = smem_base + 8;
    const uint32_t sh_base = smem_base + 16 + SW_FLOATS * 4;  // s_h byte addr

    // stage weights: s_W[k][pc] = Wg[pc>>5][(256+k)*256 + rank*32 + (pc&31)]
    for (int idx = tid; idx < SW_FLOATS; idx += REC_THREADS) {
        int k = idx >> 7, pc = idx & 127;
        s_W[idx] = Wg[pc >> 5][(size_t)(256 + k) * 256 + rank * 32 + (pc & 31)];
    }
    for (int i = tid; i < SH_FLOATS; i += REC_THREADS) s_h[i] = 0.f;
    if (tid < 64) s_c[tid] = 0.f;

    if (tid == 0) {
        asm volatile("mbarrier.init.shared.b64 [%0], 1;" :: "r"(bar0) : "memory");
        asm volatile("mbarrier.init.shared.b64 [%0], 1;" :: "r"(bar1) : "memory");
        // arm boundaries 0 and 1 before ANY rank can push (cluster.sync below)
        asm volatile("mbarrier.arrive.expect_tx.shared.b64 _, [%0], %1;"
                     :: "r"(bar0), "r"(INBOX_TX) : "memory");
        asm volatile("mbarrier.arrive.expect_tx.shared.b64 _, [%0], %1;"
                     :: "r"(bar1), "r"(INBOX_TX) : "memory");
    }
    __syncthreads();
    asm volatile("barrier.cluster.arrive.aligned;" ::: "memory");
    asm volatile("barrier.cluster.wait.aligned;" ::: "memory");

    // GEMV roles: warp ks (32 k's), lane colq (4 cols), both batches
    const int ks   = tid >> 5;
    const int colq = tid & 31;

    // fused tail roles (tid < 64): b = tid>>5, u = tid&31
    const int tb = tid >> 5;
    const int tu = tid & 31;

    // push role (all 256): dest rank p = tid>>5, slice s = tid&31
    const int pp   = tid >> 5;
    const int ps   = tid & 31;
    const int pb   = ps >> 4;          // batch
    const int pq   = ps & 15;          // 2-float group within 32 units

    // Zx prefetch (tail threads): 4 gate columns for (tb, tu)
    float pf[4];
    if (tid < 64) {
        const float* z = g_Zx + ((size_t)0 * 32 + bb0 + tb) * ZCOLS + rank * 32 + tu;
        #pragma unroll
        for (int g = 0; g < 4; g++) pf[g] = __ldcg(z + g * 256);
    }

    for (int t = 0; t < T_STEPS; t++) {
        const int cbuf = t & 1, nbuf = cbuf ^ 1;

        // GEMV partial: 4 cols x 2 batches x 32 k per thread (weights reused
        // across batches -> crossbar == FMA floor)
        {
            const float* hb0 = s_h + (cbuf * 2) * 256 + ks * 32;
            const float* hb1 = hb0 + 256;
            const float* wk  = s_W + (ks * 32) * 128 + colq * 4;
            float4 A0 = make_float4(0.f, 0.f, 0.f, 0.f), A1 = A0;
            #pragma unroll
            for (int j = 0; j < 8; j++) {
                float4 h0 = *reinterpret_cast<const float4*>(hb0 + j * 4);
                float4 h1 = *reinterpret_cast<const float4*>(hb1 + j * 4);
                float4 w;
                w = *reinterpret_cast<const float4*>(wk + (j * 4 + 0) * 128);
                A0.x = fmaf(w.x, h0.x, A0.x); A0.y = fmaf(w.y, h0.x, A0.y);
                A0.z = fmaf(w.z, h0.x, A0.z); A0.w = fmaf(w.w, h0.x, A0.w);
                A1.x = fmaf(w.x, h1.x, A1.x); A1.y = fmaf(w.y, h1.x, A1.y);
                A1.z = fmaf(w.z, h1.x, A1.z); A1.w = fmaf(w.w, h1.x, A1.w);
                w = *reinterpret_cast<const float4*>(wk + (j * 4 + 1) * 128);
                A0.x = fmaf(w.x, h0.y, A0.x); A0.y = fmaf(w.y, h0.y, A0.y);
                A0.z = fmaf(w.z, h0.y, A0.z); A0.w = fmaf(w.w, h0.y, A0.w);
                A1.x = fmaf(w.x, h1.y, A1.x); A1.y = fmaf(w.y, h1.y, A1.y);
                A1.z = fmaf(w.z, h1.y, A1.z); A1.w = fmaf(w.w, h1.y, A1.w);
                w = *reinterpret_cast<const float4*>(wk + (j * 4 + 2) * 128);
                A0.x = fmaf(w.x, h0.z, A0.x); A0.y = fmaf(w.y, h0.z, A0.y);
                A0.z = fmaf(w.z, h0.z, A0.z); A0.w = fmaf(w.w, h0.z, A0.w);
                A1.x = fmaf(w.x, h1.z, A1.x); A1.y = fmaf(w.y, h1.z, A1.y);
                A1.z = fmaf(w.z, h1.z, A1.z); A1.w = fmaf(w.w, h1.z, A1.w);
                w = *reinterpret_cast<const float4*>(wk + (j * 4 + 3) * 128);
                A0.x = fmaf(w.x, h0.w, A0.x); A0.y = fmaf(w.y, h0.w, A0.y);
                A0.z = fmaf(w.z, h0.w, A0.z); A0.w = fmaf(w.w, h0.w, A0.w);
                A1.x = fmaf(w.x, h1.w, A1.x); A1.y = fmaf(w.y, h1.w, A1.y);
                A1.z = fmaf(w.z, h1.w, A1.z); A1.w = fmaf(w.w, h1.w, A1.w);
            }
            *reinterpret_cast<float4*>(s_part + (ks * 2 + 0) * 128 + colq * 4) = A0;
            *reinterpret_cast<float4*>(s_part + (ks * 2 + 1) * 128 + colq * 4) = A1;
        }
        __syncthreads();                      // s_part ready

        // fused tail: combine + gates + c,h update (64 threads)
        if (tid < 64) {
            float zf = pf[0], zi = pf[1], zo = pf[2], zg = pf[3];
            #pragma unroll
            for (int q = 0; q < 8; q++) {
                const float* pr = s_part + (q * 2 + tb) * 128;
                zf += pr[0 * 32 + tu];
                zi += pr[1 * 32 + tu];
                zo += pr[2 * 32 + tu];
                zg += pr[3 * 32 + tu];
            }
            float fg = fast_sigmoid(zf);
            float ig = fast_sigmoid(zi);
            float og = fast_sigmoid(zo);
            float gg = fast_tanh(zg);
            float cv = fmaf(fg, s_c[tid], ig * gg);
            s_c[tid] = cv;
            float hv = og * fast_tanh(cv);
            s_stage[tid] = hv;
            out[((size_t)(bb0 + tb) * T_STEPS + (T_STEPS - 1 - t)) * HID
                + rank * 32 + tu] = hv;
            // prefetch Zx(t+1)
            if (t + 1 < T_STEPS) {
                const float* z = g_Zx + ((size_t)(t + 1) * 32 + bb0 + tb) * ZCOLS
                               + rank * 32 + tu;
                #pragma unroll
                for (int g = 0; g < 4; g++) pf[g] = __ldcg(z + g * 256);
            }
        }
        __syncthreads();                      // s_stage ready for all pushers

        if (t + 1 < T_STEPS) {
            // push: every thread does ONE 8B st.async to rank pp (incl self):
            // peer s_h[nbuf][pb][rank*32 + pq*2] <- s_stage[pb][pq*2..+1]
            {
                unsigned long long val =
                    *reinterpret_cast<const unsigned long long*>(
                        s_stage + pb * 32 + pq * 2);
                uint32_t daddr = sh_base
                    + (uint32_t)(((nbuf * 2 + pb) * 256 + rank * 32 + pq * 2) * 4);
                uint32_t baddr = smem_base + (uint32_t)((t & 1) * 8);
                asm volatile(
                    "{\n\t.reg .b32 ra, rb;\n\t"
                    "mapa.shared::cluster.u32 ra, %0, %2;\n\t"
                    "mapa.shared::cluster.u32 rb, %1, %2;\n\t"
                    "st.async.shared::cluster.mbarrier::complete_tx::bytes.b64 "
                    "[ra], %3, [rb];\n\t}"
                    :: "r"(daddr), "r"(baddr), "r"(pp), "l"(val) : "memory");
            }
            // wait boundary t: parity = (t>>1)&1 on bar[t&1]
            {
                const uint32_t bar = smem_base + (uint32_t)((t & 1) * 8);
                const uint32_t par = (uint32_t)((t >> 1) & 1);
                uint32_t done = 0;
                do {
                    asm volatile(
                        "{\n\t.reg .pred p;\n\t"
                        "mbarrier.try_wait.parity.acquire.cta.shared::cta.b64 "
                        "p, [%1], %2, 0x989680;\n\t"
                        "selp.b32 %0, 1, 0, p;\n\t}"
                        : "=r"(done) : "r"(bar), "r"(par) : "memory");
                } while (!done);
            }
            // re-arm bar[t&1] for boundary t+2 (provably before any t+2 push:
            // peers need my t+1 push first, which happens a full step later)
            if (tid == 0 && t + 2 <= T_STEPS - 2) {
                const uint32_t bar = smem_base + (uint32_t)((t & 1) * 8);
                asm volatile("mbarrier.arrive.expect_tx.shared.b64 _, [%0], %1;"
                             :: "r"(bar), "r"(INBOX_TX) : "memory");
            }
        }
    }

    // DSMEM discipline: no CTA exits while peers could still target it
    asm volatile("barrier.cluster.arrive.aligned;" ::: "memory");
    asm volatile("barrier.cluster.wait.aligned;" ::: "memory");
}

// ============================================================================
extern "C" void kernel_launch(void* const* d_in, const int* in_sizes, int n_in,
                              void* d_out, int out_size)
{
    const float* x  = (const float*)d_in[0];
    const float* Wf = (const float*)d_in[1];
    const float* bf = (const float*)d_in[2];
    const float* Wi = (const float*)d_in[3];
    const float* bi = (const float*)d_in[4];
    const float* Wo = (const float*)d_in[5];
    const float* bo = (const float*)d_in[6];
    const float* Wc = (const float*)d_in[7];
    const float* bc = (const float*)d_in[8];
    float* out = (float*)d_out;

    cudaFuncSetAttribute(lstm_rec,
                         cudaFuncAttributeMaxDynamicSharedMemorySize, SMEM_BYTES);

    dim3 g1(ZCOLS / 128, MROWS / 128);   // 8 x 512
    gemm_zx<<<g1, 256>>>(x, Wf, bf, Wi, bi, Wo, bo, Wc, bc);
    lstm_rec<<<REC_CTAS, REC_THREADS, SMEM_BYTES>>>(Wf, Wi, Wo, Wc, out);
}

// round 8
// speedup vs baseline: 1.4372x; 1.0487x over previous
#include <cuda_runtime.h>
#include <math.h>
#include <stdint.h>

#define T_STEPS 2048
#define BATCH   32
#define HID     256
#define ZCOLS   1024            // 4*HID, gate order f,i,o,c
#define MROWS   (T_STEPS * BATCH)
#define CLUSTER 8
#define REC_CTAS 128            // 16 clusters x 8 CTAs
#define REC_THREADS 256

// ---------------- scratch (device globals: no allocations allowed) ----------
__device__ float g_Zx[(size_t)MROWS * ZCOLS];   // row-major: Zx[t*32+b][col]

// ============================================================================
// Kernel 1: Zx[t*32+b][g*256+j] = sum_k x[b][t][k] * Wg[k][j] + bg[j]
// 128x128 tile SGEMM, BK=16, 256 threads, 8x8 microtile. (~fp32 roofline)
// ============================================================================
__global__ __launch_bounds__(256, 2)
void gemm_zx(const float* __restrict__ x,
             const float* __restrict__ Wf, const float* __restrict__ bf,
             const float* __restrict__ Wi, const float* __restrict__ bi,
             const float* __restrict__ Wo, const float* __restrict__ bo,
             const float* __restrict__ Wc, const float* __restrict__ bc)
{
    __shared__ float As[16 * 128];   // [k][m]
    __shared__ float Bs[16 * 128];   // [k][n]

    const int t = threadIdx.x;

    const float* Wg[4] = {Wf, Wi, Wo, Wc};
    const float* bg[4] = {bf, bi, bo, bc};

    const int N0 = blockIdx.x * 128;          // never straddles a gate
    const int gate = N0 >> 8;
    const int jb = N0 & 255;
    const float* __restrict__ W = Wg[gate];

    const int M0 = blockIdx.y * 128;
    const int tx = t & 15;
    const int ty = t >> 4;

    float acc[8][8];
    #pragma unroll
    for (int i = 0; i < 8; i++)
        #pragma unroll
        for (int j = 0; j < 8; j++) acc[i][j] = 0.f;

    for (int k0 = 0; k0 < 256; k0 += 16) {
        #pragma unroll
        for (int i = 0; i < 2; i++) {
            int f = t + i * 256;
            int kq  = f >> 7;
            int row = f & 127;
            int m   = M0 + row;
            int bb  = m & 31;
            int tt  = m >> 5;
            float4 a = *reinterpret_cast<const float4*>(
                x + ((size_t)bb * T_STEPS + tt) * 256 + k0 + kq * 4);
            As[(kq * 4 + 0) * 128 + row] = a.x;
            As[(kq * 4 + 1) * 128 + row] = a.y;
            As[(kq * 4 + 2) * 128 + row] = a.z;
            As[(kq * 4 + 3) * 128 + row] = a.w;
            int kk = f >> 5;
            int nq = f & 31;
            *reinterpret_cast<float4*>(&Bs[kk * 128 + nq * 4]) =
                *reinterpret_cast<const float4*>(W + (size_t)(k0 + kk) * 256 + jb + nq * 4);
        }
        __syncthreads();

        #pragma unroll
        for (int k = 0; k < 16; k++) {
            float a[8], bv[8];
            *reinterpret_cast<float4*>(&a[0])  = *reinterpret_cast<float4*>(&As[k * 128 + ty * 8]);
            *reinterpret_cast<float4*>(&a[4])  = *reinterpret_cast<float4*>(&As[k * 128 + ty * 8 + 4]);
            *reinterpret_cast<float4*>(&bv[0]) = *reinterpret_cast<float4*>(&Bs[k * 128 + tx * 8]);
            *reinterpret_cast<float4*>(&bv[4]) = *reinterpret_cast<float4*>(&Bs[k * 128 + tx * 8 + 4]);
            #pragma unroll
            for (int i = 0; i < 8; i++)
                #pragma unroll
                for (int j = 0; j < 8; j++)
                    acc[i][j] = fmaf(a[i], bv[j], acc[i][j]);
        }
        __syncthreads();
    }

    const float* __restrict__ bias = bg[gate];
    #pragma unroll
    for (int i = 0; i < 8; i++) {
        int m = M0 + ty * 8 + i;
        float* zr = g_Zx + (size_t)m * ZCOLS + N0 + tx * 8;
        float4 v0, v1;
        v0.x = acc[i][0] + bias[jb + tx * 8 + 0];
        v0.y = acc[i][1] + bias[jb + tx * 8 + 1];
        v0.z = acc[i][2] + bias[jb + tx * 8 + 2];
        v0.w = acc[i][3] + bias[jb + tx * 8 + 3];
        v1.x = acc[i][4] + bias[jb + tx * 8 + 4];
        v1.y = acc[i][5] + bias[jb + tx * 8 + 5];
        v1.z = acc[i][6] + bias[jb + tx * 8 + 6];
        v1.w = acc[i][7] + bias[jb + tx * 8 + 7];
        *reinterpret_cast<float4*>(zr)     = v0;
        *reinterpret_cast<float4*>(zr + 4) = v1;
    }
}

// ============================================================================
// Kernel 2: cluster recurrence, per-source slice barriers.
// 16 clusters x 8 CTAs; cluster = 2 batches; CTA owns 32 units x 4 gates.
// Each dest has 8x2 mbarriers: bar(src, t&1), each boundary = 256B from src.
// Warp ks consumes k-range [32ks, 32ks+32) = exactly src ks's slice, so it
// waits ONLY bar(ks) -> GEMV starts on first-arrival, skew absorbed.
// ============================================================================
__device__ __forceinline__ uint32_t smem_u32(const void* p) {
    uint32_t a;
    asm("{ .reg .u64 t; cvta.to.shared.u64 t, %1; cvt.u32.u64 %0, t; }"
        : "=r"(a) : "l"(p));
    return a;
}

__device__ __forceinline__ float fast_sigmoid(float z) {
    return __fdividef(1.f, 1.f + __expf(-z));
}
__device__ __forceinline__ float fast_tanh(float z) {
    return 1.f - __fdividef(2.f, __expf(2.f * z) + 1.f);
}

// smem layout: 16 mbarriers (128B), then floats
#define NBARS       16                   // 8 src x 2 (ping-pong)
#define SLICE_TX    256                  // bytes per (src, boundary)
#define SW_FLOATS   (256 * 128)          // weights [k][pc], pc = gate*32 + ul
#define SH_FLOATS   (2 * 2 * 256)        // h [buf][b][k]  (written by st.async)
#define SP_FLOATS   (8 * 2 * 128)        // partials [ks][b][pc], x2 buffers
#define SC_FLOATS   (2 * 32)             // cell state [b][u]
#define SMEM_FLOATS (SW_FLOATS + SH_FLOATS + 2 * SP_FLOATS + SC_FLOATS)
#define SMEM_BYTES  (NBARS * 8 + SMEM_FLOATS * 4)

__global__ __launch_bounds__(REC_THREADS, 1) __cluster_dims__(CLUSTER, 1, 1)
void lstm_rec(const float* __restrict__ Wf, const float* __restrict__ Wi,
              const float* __restrict__ Wo, const float* __restrict__ Wc,
              float* __restrict__ out)
{
    extern __shared__ float smem_raw[];
    float* s_W    = smem_raw + NBARS * 2;     // [256][128]
    float* s_h    = s_W + SW_FLOATS;          // [2][2][256]
    float* s_part = s_h + SH_FLOATS;          // [2][8][2][128]
    float* s_c    = s_part + 2 * SP_FLOATS;   // [2][32]

    const int tid  = threadIdx.x;
    const int rank = blockIdx.x & (CLUSTER - 1);
    const int cid  = blockIdx.x >> 3;
    const int bb0  = cid * 2;
    const float* Wg[4] = {Wf, Wi, Wo, Wc};

    const uint32_t smem_base = smem_u32(smem_raw);
    const uint32_t sh_base = smem_base + NBARS * 8 + SW_FLOATS * 4;
    // bar(src, pp) local address
    #define BAR_ADDR(src, pp) (smem_base + (uint32_t)(((src) * 2 + (pp)) * 8))

    // stage weights: s_W[k][pc] = Wg[pc>>5][(256+k)*256 + rank*32 + (pc&31)]
    for (int idx = tid; idx < SW_FLOATS; idx += REC_THREADS) {
        int k = idx >> 7, pc = idx & 127;
        s_W[idx] = Wg[pc >> 5][(size_t)(256 + k) * 256 + rank * 32 + (pc & 31)];
    }
    for (int i = tid; i < SH_FLOATS; i += REC_THREADS) s_h[i] = 0.f;
    if (tid < 64) s_c[tid] = 0.f;

    if (tid == 0) {
        #pragma unroll
        for (int i = 0; i < NBARS; i++) {
            uint32_t b = smem_base + (uint32_t)(i * 8);
            asm volatile("mbarrier.init.shared.b64 [%0], 1;" :: "r"(b) : "memory");
            asm volatile("mbarrier.arrive.expect_tx.shared.b64 _, [%0], %1;"
                         :: "r"(b), "r"(SLICE_TX) : "memory");
        }
    }
    __syncthreads();
    asm volatile("barrier.cluster.arrive.aligned;" ::: "memory");
    asm volatile("barrier.cluster.wait.aligned;" ::: "memory");

    // GEMV roles: warp ks (32 k's = src ks's slice), lane colq (4 cols)
    const int ks   = tid >> 5;
    const int colq = tid & 31;
    const int lane = tid & 31;

    // tail roles (tid < 64): tb = batch, tu = unit
    const int tb = tid >> 5;
    const int tu = tid & 31;

    // per-warp barrier phase state (uniform across lanes of a warp)
    int par0 = 0, par1 = 0;

    // Zx prefetch (tail threads)
    float pf[4];
    if (tid < 64) {
        const float* z = g_Zx + ((size_t)0 * 32 + bb0 + tb) * ZCOLS + rank * 32 + tu;
        #pragma unroll
        for (int g = 0; g < 4; g++) pf[g] = __ldcg(z + g * 256);
    }

    for (int t = 0; t < T_STEPS; t++) {
        const int cbuf = t & 1, nbuf = cbuf ^ 1;

        // wait for THIS warp's slice (boundary t), t >= 1
        if (t >= 1) {
            const uint32_t bar = BAR_ADDR(ks, t & 1);
            const int par = (t & 1) ? par1 : par0;
            uint32_t done = 0;
            do {
                asm volatile(
                    "{\n\t.reg .pred p;\n\t"
                    "mbarrier.try_wait.parity.acquire.cta.shared::cta.b64 "
                    "p, [%1], %2, 0x989680;\n\t"
                    "selp.b32 %0, 1, 0, p;\n\t}"
                    : "=r"(done) : "r"(bar), "r"(par) : "memory");
            } while (!done);
            if (t & 1) par1 ^= 1; else par0 ^= 1;
            // re-arm this bar for boundary t+2 (only this warp touches it;
            // any t+2 push transitively requires my t+1 push, which is later)
            if (lane == 0 && t + 2 < T_STEPS) {
                asm volatile("mbarrier.arrive.expect_tx.shared.b64 _, [%0], %1;"
                             :: "r"(bar), "r"(SLICE_TX) : "memory");
            }
        }

        // GEMV partial: 4 cols x 2 batches x 32 k per thread
        {
            const float* hb0 = s_h + (cbuf * 2) * 256 + ks * 32;
            const float* hb1 = hb0 + 256;
            const float* wk  = s_W + (ks * 32) * 128 + colq * 4;
            float4 A0 = make_float4(0.f, 0.f, 0.f, 0.f), A1 = A0;
            #pragma unroll
            for (int j = 0; j < 8; j++) {
                float4 h0 = *reinterpret_cast<const float4*>(hb0 + j * 4);
                float4 h1 = *reinterpret_cast<const float4*>(hb1 + j * 4);
                float4 w;
                w = *reinterpret_cast<const float4*>(wk + (j * 4 + 0) * 128);
                A0.x = fmaf(w.x, h0.x, A0.x); A0.y = fmaf(w.y, h0.x, A0.y);
                A0.z = fmaf(w.z, h0.x, A0.z); A0.w = fmaf(w.w, h0.x, A0.w);
                A1.x = fmaf(w.x, h1.x, A1.x); A1.y = fmaf(w.y, h1.x, A1.y);
                A1.z = fmaf(w.z, h1.x, A1.z); A1.w = fmaf(w.w, h1.x, A1.w);
                w = *reinterpret_cast<const float4*>(wk + (j * 4 + 1) * 128);
                A0.x = fmaf(w.x, h0.y, A0.x); A0.y = fmaf(w.y, h0.y, A0.y);
                A0.z = fmaf(w.z, h0.y, A0.z); A0.w = fmaf(w.w, h0.y, A0.w);
                A1.x = fmaf(w.x, h1.y, A1.x); A1.y = fmaf(w.y, h1.y, A1.y);
                A1.z = fmaf(w.z, h1.y, A1.z); A1.w = fmaf(w.w, h1.y, A1.w);
                w = *reinterpret_cast<const float4*>(wk + (j * 4 + 2) * 128);
                A0.x = fmaf(w.x, h0.z, A0.x); A0.y = fmaf(w.y, h0.z, A0.y);
                A0.z = fmaf(w.z, h0.z, A0.z); A0.w = fmaf(w.w, h0.z, A0.w);
                A1.x = fmaf(w.x, h1.z, A1.x); A1.y = fmaf(w.y, h1.z, A1.y);
                A1.z = fmaf(w.z, h1.z, A1.z); A1.w = fmaf(w.w, h1.z, A1.w);
                w = *reinterpret_cast<const float4*>(wk + (j * 4 + 3) * 128);
                A0.x = fmaf(w.x, h0.w, A0.x); A0.y = fmaf(w.y, h0.w, A0.y);
                A0.z = fmaf(w.z, h0.w, A0.z); A0.w = fmaf(w.w, h0.w, A0.w);
                A1.x = fmaf(w.x, h1.w, A1.x); A1.y = fmaf(w.y, h1.w, A1.y);
                A1.z = fmaf(w.z, h1.w, A1.z); A1.w = fmaf(w.w, h1.w, A1.w);
            }
            float* pw = s_part + cbuf * SP_FLOATS + (ks * 2) * 128 + colq * 4;
            *reinterpret_cast<float4*>(pw)       = A0;
            *reinterpret_cast<float4*>(pw + 128) = A1;
        }
        __syncthreads();                      // s_part[cbuf] complete

        // fused tail (64 threads): combine + gates + c,h + push + out
        if (tid < 64) {
            float zf = pf[0], zi = pf[1], zo = pf[2], zg = pf[3];
            const float* pb = s_part + cbuf * SP_FLOATS + tb * 128;
            #pragma unroll
            for (int q = 0; q < 8; q++) {
                const float* pr = pb + q * 256;
                zf += pr[0 * 32 + tu];
                zi += pr[1 * 32 + tu];
                zo += pr[2 * 32 + tu];
                zg += pr[3 * 32 + tu];
            }
            float fg = fast_sigmoid(zf);
            float ig = fast_sigmoid(zi);
            float og = fast_sigmoid(zo);
            float gg = fast_tanh(zg);
            float cv = fmaf(fg, s_c[tid], ig * gg);
            s_c[tid] = cv;
            float hv = og * fast_tanh(cv);

            // push FIRST (unblocks peers): lane-paired 8B st.async to 8 ranks
            if (t + 1 < T_STEPS) {
                float hp = __shfl_xor_sync(0xffffffffu, hv, 1);
                if ((tu & 1) == 0) {
                    double val;
                    {
                        float2 f2 = make_float2(hv, hp);
                        val = *reinterpret_cast<double*>(&f2);
                    }
                    uint32_t daddr = sh_base
                        + (uint32_t)(((nbuf * 2 + tb) * 256 + rank * 32 + tu) * 4);
                    uint32_t baddr = BAR_ADDR(rank, (t + 1) & 1);
                    #pragma unroll
                    for (int p = 0; p < CLUSTER; p++) {
                        asm volatile(
                            "{\n\t.reg .b32 ra, rb;\n\t"
                            "mapa.shared::cluster.u32 ra, %0, %2;\n\t"
                            "mapa.shared::cluster.u32 rb, %1, %2;\n\t"
                            "st.async.shared::cluster.mbarrier::complete_tx::bytes.b64 "
                            "[ra], %3, [rb];\n\t}"
                            :: "r"(daddr), "r"(baddr), "r"(p), "d"(val) : "memory");
                    }
                }
            }

            // output (fire-and-forget)
            out[((size_t)(bb0 + tb) * T_STEPS + (T_STEPS - 1 - t)) * HID
                + rank * 32 + tu] = hv;

            // prefetch Zx(t+1)
            if (t + 1 < T_STEPS) {
                const float* z = g_Zx + ((size_t)(t + 1) * 32 + bb0 + tb) * ZCOLS
                               + rank * 32 + tu;
                #pragma unroll
                for (int g = 0; g < 4; g++) pf[g] = __ldcg(z + g * 256);
            }
        }
        // no second syncthreads: s_part double-buffered; s_h ping-pong; the
        // t+2 overwrite of either is transitively ordered after my tail t.
    }

    // DSMEM discipline: no CTA exits while peers could still target it
    asm volatile("barrier.cluster.arrive.aligned;" ::: "memory");
    asm volatile("barrier.cluster.wait.aligned;" ::: "memory");
}

// ============================================================================
extern "C" void kernel_launch(void* const* d_in, const int* in_sizes, int n_in,
                              void* d_out, int out_size)
{
    const float* x  = (const float*)d_in[0];
    const float* Wf = (const float*)d_in[1];
    const float* bf = (const float*)d_in[2];
    const float* Wi = (const float*)d_in[3];
    const float* bi = (const float*)d_in[4];
    const float* Wo = (const float*)d_in[5];
    const float* bo = (const float*)d_in[6];
    const float* Wc = (const float*)d_in[7];
    const float* bc = (const float*)d_in[8];
    float* out = (float*)d_out;

    cudaFuncSetAttribute(lstm_rec,
                         cudaFuncAttributeMaxDynamicSharedMemorySize, SMEM_BYTES);

    dim3 g1(ZCOLS / 128, MROWS / 128);   // 8 x 512
    gemm_zx<<<g1, 256>>>(x, Wf, bf, Wi, bi, Wo, bo, Wc, bc);
    lstm_rec<<<REC_CTAS, REC_THREADS, SMEM_BYTES>>>(Wf, Wi, Wo, Wc, out);
}

// round 9
// speedup vs baseline: 1.8192x; 1.2658x over previous
#include <cuda_runtime.h>
#include <math.h>
#include <stdint.h>

#define T_STEPS 2048
#define BATCH   32
#define HID     256
#define ZCOLS   1024            // 4*HID, gate order f,i,o,c
#define MROWS   (T_STEPS * BATCH)
#define CLUSTER 8
#define REC_CTAS 128            // 16 clusters x 8 CTAs
#define REC_THREADS 256

// ---------------- scratch (device globals: no allocations allowed) ----------
__device__ float g_Zx[(size_t)MROWS * ZCOLS];   // row-major: Zx[t*32+b][col]

// ============================================================================
// Kernel 1: Zx[t*32+b][g*256+j] = sum_k x[b][t][k] * Wg[k][j] + bg[j]
// 128x128 tile SGEMM, BK=16, 256 threads, 8x8 microtile. (~fp32 roofline)
// ============================================================================
__global__ __launch_bounds__(256, 2)
void gemm_zx(const float* __restrict__ x,
             const float* __restrict__ Wf, const float* __restrict__ bf,
             const float* __restrict__ Wi, const float* __restrict__ bi,
             const float* __restrict__ Wo, const float* __restrict__ bo,
             const float* __restrict__ Wc, const float* __restrict__ bc)
{
    __shared__ float As[16 * 128];   // [k][m]
    __shared__ float Bs[16 * 128];   // [k][n]

    const int t = threadIdx.x;

    const float* Wg[4] = {Wf, Wi, Wo, Wc};
    const float* bg[4] = {bf, bi, bo, bc};

    const int N0 = blockIdx.x * 128;          // never straddles a gate
    const int gate = N0 >> 8;
    const int jb = N0 & 255;
    const float* __restrict__ W = Wg[gate];

    const int M0 = blockIdx.y * 128;
    const int tx = t & 15;
    const int ty = t >> 4;

    float acc[8][8];
    #pragma unroll
    for (int i = 0; i < 8; i++)
        #pragma unroll
        for (int j = 0; j < 8; j++) acc[i][j] = 0.f;

    for (int k0 = 0; k0 < 256; k0 += 16) {
        #pragma unroll
        for (int i = 0; i < 2; i++) {
            int f = t + i * 256;
            int kq  = f >> 7;
            int row = f & 127;
            int m   = M0 + row;
            int bb  = m & 31;
            int tt  = m >> 5;
            float4 a = *reinterpret_cast<const float4*>(
                x + ((size_t)bb * T_STEPS + tt) * 256 + k0 + kq * 4);
            As[(kq * 4 + 0) * 128 + row] = a.x;
            As[(kq * 4 + 1) * 128 + row] = a.y;
            As[(kq * 4 + 2) * 128 + row] = a.z;
            As[(kq * 4 + 3) * 128 + row] = a.w;
            int kk = f >> 5;
            int nq = f & 31;
            *reinterpret_cast<float4*>(&Bs[kk * 128 + nq * 4]) =
                *reinterpret_cast<const float4*>(W + (size_t)(k0 + kk) * 256 + jb + nq * 4);
        }
        __syncthreads();

        #pragma unroll
        for (int k = 0; k < 16; k++) {
            float a[8], bv[8];
            *reinterpret_cast<float4*>(&a[0])  = *reinterpret_cast<float4*>(&As[k * 128 + ty * 8]);
            *reinterpret_cast<float4*>(&a[4])  = *reinterpret_cast<float4*>(&As[k * 128 + ty * 8 + 4]);
            *reinterpret_cast<float4*>(&bv[0]) = *reinterpret_cast<float4*>(&Bs[k * 128 + tx * 8]);
            *reinterpret_cast<float4*>(&bv[4]) = *reinterpret_cast<float4*>(&Bs[k * 128 + tx * 8 + 4]);
            #pragma unroll
            for (int i = 0; i < 8; i++)
                #pragma unroll
                for (int j = 0; j < 8; j++)
                    acc[i][j] = fmaf(a[i], bv[j], acc[i][j]);
        }
        __syncthreads();
    }

    const float* __restrict__ bias = bg[gate];
    #pragma unroll
    for (int i = 0; i < 8; i++) {
        int m = M0 + ty * 8 + i;
        float* zr = g_Zx + (size_t)m * ZCOLS + N0 + tx * 8;
        float4 v0, v1;
        v0.x = acc[i][0] + bias[jb + tx * 8 + 0];
        v0.y = acc[i][1] + bias[jb + tx * 8 + 1];
        v0.z = acc[i][2] + bias[jb + tx * 8 + 2];
        v0.w = acc[i][3] + bias[jb + tx * 8 + 3];
        v1.x = acc[i][4] + bias[jb + tx * 8 + 4];
        v1.y = acc[i][5] + bias[jb + tx * 8 + 5];
        v1.z = acc[i][6] + bias[jb + tx * 8 + 6];
        v1.w = acc[i][7] + bias[jb + tx * 8 + 7];
        *reinterpret_cast<float4*>(zr)     = v0;
        *reinterpret_cast<float4*>(zr + 4) = v1;
    }
}

// ============================================================================
// Kernel 2: cluster recurrence; weights REGISTER-RESIDENT, FFMA2 inner loop.
// 16 clusters x 8 CTAs; cluster = 2 batches; CTA owns 32 units x 4 gates.
// Per-source slice mbarriers + st.async exchange (proven R8 protocol).
// ============================================================================
__device__ __forceinline__ uint32_t smem_u32(const void* p) {
    uint32_t a;
    asm("{ .reg .u64 t; cvta.to.shared.u64 t, %1; cvt.u32.u64 %0, t; }"
        : "=r"(a) : "l"(p));
    return a;
}

__device__ __forceinline__ float fast_sigmoid(float z) {
    return __fdividef(1.f, 1.f + __expf(-z));
}
__device__ __forceinline__ float fast_tanh(float z) {
    return 1.f - __fdividef(2.f, __expf(2.f * z) + 1.f);
}

// packed f32x2 fma: d = a*b + d (elementwise on two floats in a 64-bit reg)
#define FMA2(d, a, b) \
    asm("fma.rn.f32x2 %0, %1, %2, %3;" : "=l"(d) : "l"(a), "l"(b), "l"(d))

__device__ __forceinline__ unsigned long long pack_f2(float lo, float hi) {
    float2 f = make_float2(lo, hi);
    return *reinterpret_cast<unsigned long long*>(&f);
}
__device__ __forceinline__ float unpack_sum(unsigned long long v) {
    float2 f = *reinterpret_cast<float2*>(&v);
    return f.x + f.y;
}

// smem layout: 16 mbarriers (128B), then floats
#define NBARS       16                   // 8 src x 2 (ping-pong)
#define SLICE_TX    256                  // bytes per (src, boundary)
#define SW_FLOATS   (256 * 128)          // weights [k][pc] (staging only)
#define SH_FLOATS   (2 * 2 * 256)        // h [buf][b][k]  (written by st.async)
#define SP_FLOATS   (8 * 2 * 128)        // partials [ks][b][pc], x2 buffers
#define SC_FLOATS   (2 * 32)             // cell state [b][u]
#define SMEM_FLOATS (SW_FLOATS + SH_FLOATS + 2 * SP_FLOATS + SC_FLOATS)
#define SMEM_BYTES  (NBARS * 8 + SMEM_FLOATS * 4)

__global__ __launch_bounds__(REC_THREADS, 1) __cluster_dims__(CLUSTER, 1, 1)
void lstm_rec(const float* __restrict__ Wf, const float* __restrict__ Wi,
              const float* __restrict__ Wo, const float* __restrict__ Wc,
              float* __restrict__ out)
{
    extern __shared__ float smem_raw[];
    float* s_W    = smem_raw + NBARS * 2;     // [256][128] (staging)
    float* s_h    = s_W + SW_FLOATS;          // [2][2][256]
    float* s_part = s_h + SH_FLOATS;          // [2][8][2][128]
    float* s_c    = s_part + 2 * SP_FLOATS;   // [2][32]

    const int tid  = threadIdx.x;
    const int rank = blockIdx.x & (CLUSTER - 1);
    const int cid  = blockIdx.x >> 3;
    const int bb0  = cid * 2;
    const float* Wg[4] = {Wf, Wi, Wo, Wc};

    const uint32_t smem_base = smem_u32(smem_raw);
    const uint32_t sh_base = smem_base + NBARS * 8 + SW_FLOATS * 4;
    #define BAR_ADDR(src, pp) (smem_base + (uint32_t)(((src) * 2 + (pp)) * 8))

    // stage weights once: s_W[k][pc] = Wg[pc>>5][(256+k)*256 + rank*32 + (pc&31)]
    for (int idx = tid; idx < SW_FLOATS; idx += REC_THREADS) {
        int k = idx >> 7, pc = idx & 127;
        s_W[idx] = Wg[pc >> 5][(size_t)(256 + k) * 256 + rank * 32 + (pc & 31)];
    }
    for (int i = tid; i < SH_FLOATS; i += REC_THREADS) s_h[i] = 0.f;
    if (tid < 64) s_c[tid] = 0.f;

    if (tid == 0) {
        #pragma unroll
        for (int i = 0; i < NBARS; i++) {
            uint32_t b = smem_base + (uint32_t)(i * 8);
            asm volatile("mbarrier.init.shared.b64 [%0], 1;" :: "r"(b) : "memory");
            asm volatile("mbarrier.arrive.expect_tx.shared.b64 _, [%0], %1;"
                         :: "r"(b), "r"(SLICE_TX) : "memory");
        }
    }
    __syncthreads();

    // GEMV roles: warp ks (32 k's = src ks's slice), lane colq (4 cols)
    const int ks   = tid >> 5;
    const int colq = tid & 31;
    const int lane = tid & 31;

    // hoist this thread's 128 weights into registers, packed over k-parity:
    // wreg[c][p] = (W[k=2p][col], W[k=2p+1][col]), col = colq*4+c, k rel ks*32
    unsigned long long wreg[4][16];
    #pragma unroll
    for (int c = 0; c < 4; c++)
        #pragma unroll
        for (int p = 0; p < 16; p++)
            wreg[c][p] = pack_f2(
                s_W[(ks * 32 + 2 * p)     * 128 + colq * 4 + c],
                s_W[(ks * 32 + 2 * p + 1) * 128 + colq * 4 + c]);

    asm volatile("barrier.cluster.arrive.aligned;" ::: "memory");
    asm volatile("barrier.cluster.wait.aligned;" ::: "memory");

    // tail roles (tid < 64): tb = batch, tu = unit
    const int tb = tid >> 5;
    const int tu = tid & 31;

    // per-warp barrier phase state
    int par0 = 0, par1 = 0;

    // Zx prefetch (tail threads)
    float pf[4];
    if (tid < 64) {
        const float* z = g_Zx + ((size_t)0 * 32 + bb0 + tb) * ZCOLS + rank * 32 + tu;
        #pragma unroll
        for (int g = 0; g < 4; g++) pf[g] = __ldcg(z + g * 256);
    }

    for (int t = 0; t < T_STEPS; t++) {
        const int cbuf = t & 1, nbuf = cbuf ^ 1;

        // wait for THIS warp's slice (boundary t), t >= 1
        if (t >= 1) {
            const uint32_t bar = BAR_ADDR(ks, t & 1);
            const int par = (t & 1) ? par1 : par0;
            uint32_t done = 0;
            do {
                asm volatile(
                    "{\n\t.reg .pred p;\n\t"
                    "mbarrier.try_wait.parity.acquire.cta.shared::cta.b64 "
                    "p, [%1], %2, 0x989680;\n\t"
                    "selp.b32 %0, 1, 0, p;\n\t}"
                    : "=r"(done) : "r"(bar), "r"(par) : "memory");
            } while (!done);
            if (t & 1) par1 ^= 1; else par0 ^= 1;
            if (lane == 0 && t + 2 < T_STEPS) {
                asm volatile("mbarrier.arrive.expect_tx.shared.b64 _, [%0], %1;"
                             :: "r"(bar), "r"(SLICE_TX) : "memory");
            }
        }

        // GEMV: 4 cols x 2 batches x 32 k; weights in regs, FFMA2 packed
        {
            const float* hb0 = s_h + (cbuf * 2) * 256 + ks * 32;
            const float* hb1 = hb0 + 256;
            unsigned long long acc[4][2];
            #pragma unroll
            for (int c = 0; c < 4; c++) { acc[c][0] = 0ull; acc[c][1] = 0ull; }

            #pragma unroll
            for (int j = 0; j < 8; j++) {
                // float4 = k 4j..4j+3 = packed pairs (2j), (2j+1)
                ulonglong2 H0 = *reinterpret_cast<const ulonglong2*>(hb0 + j * 4);
                ulonglong2 H1 = *reinterpret_cast<const ulonglong2*>(hb1 + j * 4);
                #pragma unroll
                for (int c = 0; c < 4; c++) {
                    FMA2(acc[c][0], wreg[c][2 * j],     H0.x);
                    FMA2(acc[c][0], wreg[c][2 * j + 1], H0.y);
                    FMA2(acc[c][1], wreg[c][2 * j],     H1.x);
                    FMA2(acc[c][1], wreg[c][2 * j + 1], H1.y);
                }
            }
            float* pw = s_part + cbuf * SP_FLOATS + (ks * 2) * 128 + colq * 4;
            float4 A0, A1;
            A0.x = unpack_sum(acc[0][0]); A0.y = unpack_sum(acc[1][0]);
            A0.z = unpack_sum(acc[2][0]); A0.w = unpack_sum(acc[3][0]);
            A1.x = unpack_sum(acc[0][1]); A1.y = unpack_sum(acc[1][1]);
            A1.z = unpack_sum(acc[2][1]); A1.w = unpack_sum(acc[3][1]);
            *reinterpret_cast<float4*>(pw)       = A0;
            *reinterpret_cast<float4*>(pw + 128) = A1;
        }
        __syncthreads();                      // s_part[cbuf] complete

        // fused tail (64 threads): combine + gates + c,h + push + out
        if (tid < 64) {
            float zf = pf[0], zi = pf[1], zo = pf[2], zg = pf[3];
            const float* pb = s_part + cbuf * SP_FLOATS + tb * 128;
            #pragma unroll
            for (int q = 0; q < 8; q++) {
                const float* pr = pb + q * 256;
                zf += pr[0 * 32 + tu];
                zi += pr[1 * 32 + tu];
                zo += pr[2 * 32 + tu];
                zg += pr[3 * 32 + tu];
            }
            float fg = fast_sigmoid(zf);
            float ig = fast_sigmoid(zi);
            float og = fast_sigmoid(zo);
            float gg = fast_tanh(zg);
            float cv = fmaf(fg, s_c[tid], ig * gg);
            s_c[tid] = cv;
            float hv = og * fast_tanh(cv);

            // push FIRST (unblocks peers): lane-paired 8B st.async to 8 ranks
            if (t + 1 < T_STEPS) {
                float hp = __shfl_xor_sync(0xffffffffu, hv, 1);
                if ((tu & 1) == 0) {
                    double val;
                    {
                        float2 f2 = make_float2(hv, hp);
                        val = *reinterpret_cast<double*>(&f2);
                    }
                    uint32_t daddr = sh_base
                        + (uint32_t)(((nbuf * 2 + tb) * 256 + rank * 32 + tu) * 4);
                    uint32_t baddr = BAR_ADDR(rank, (t + 1) & 1);
                    #pragma unroll
                    for (int p = 0; p < CLUSTER; p++) {
                        asm volatile(
                            "{\n\t.reg .b32 ra, rb;\n\t"
                            "mapa.shared::cluster.u32 ra, %0, %2;\n\t"
                            "mapa.shared::cluster.u32 rb, %1, %2;\n\t"
                            "st.async.shared::cluster.mbarrier::complete_tx::bytes.b64 "
                            "[ra], %3, [rb];\n\t}"
                            :: "r"(daddr), "r"(baddr), "r"(p), "d"(val) : "memory");
                    }
                }
            }

            // output (fire-and-forget)
            out[((size_t)(bb0 + tb) * T_STEPS + (T_STEPS - 1 - t)) * HID
                + rank * 32 + tu] = hv;

            // prefetch Zx(t+1)
            if (t + 1 < T_STEPS) {
                const float* z = g_Zx + ((size_t)(t + 1) * 32 + bb0 + tb) * ZCOLS
                               + rank * 32 + tu;
                #pragma unroll
                for (int g = 0; g < 4; g++) pf[g] = __ldcg(z + g * 256);
            }
        }
        // no second syncthreads: s_part double-buffered; s_h ping-pong; any
        // t+2 overwrite is transitively ordered after my tail of step t.
    }

    // DSMEM discipline: no CTA exits while peers could still target it
    asm volatile("barrier.cluster.arrive.aligned;" ::: "memory");
    asm volatile("barrier.cluster.wait.aligned;" ::: "memory");
}

// ============================================================================
extern "C" void kernel_launch(void* const* d_in, const int* in_sizes, int n_in,
                              void* d_out, int out_size)
{
    const float* x  = (const float*)d_in[0];
    const float* Wf = (const float*)d_in[1];
    const float* bf = (const float*)d_in[2];
    const float* Wi = (const float*)d_in[3];
    const float* bi = (const float*)d_in[4];
    const float* Wo = (const float*)d_in[5];
    const float* bo = (const float*)d_in[6];
    const float* Wc = (const float*)d_in[7];
    const float* bc = (const float*)d_in[8];
    float* out = (float*)d_out;

    cudaFuncSetAttribute(lstm_rec,
                         cudaFuncAttributeMaxDynamicSharedMemorySize, SMEM_BYTES);

    dim3 g1(ZCOLS / 128, MROWS / 128);   // 8 x 512
    gemm_zx<<<g1, 256>>>(x, Wf, bf, Wi, bi, Wo, bo, Wc, bc);
    lstm_rec<<<REC_CTAS, REC_THREADS, SMEM_BYTES>>>(Wf, Wi, Wo, Wc, out);
}

// round 10
// speedup vs baseline: 1.8574x; 1.0210x over previous
#include <cuda_runtime.h>
#include <math.h>
#include <stdint.h>

#define T_STEPS 2048
#define BATCH   32
#define HID     256
#define ZCOLS   1024            // 4*HID, gate order f,i,o,c
#define MROWS   (T_STEPS * BATCH)
#define CLUSTER 8
#define REC_CTAS 128            // 16 clusters x 8 CTAs
#define REC_THREADS 256

// ---------------- scratch (device globals: no allocations allowed) ----------
__device__ float g_Zx[(size_t)MROWS * ZCOLS];   // row-major: Zx[t*32+b][col]

// ============================================================================
// Kernel 1: Zx[t*32+b][g*256+j] = sum_k x[b][t][k] * Wg[k][j] + bg[j]
// 128x128 tile SGEMM, BK=16, 256 threads, 8x8 microtile. (at fp32 roofline)
// ============================================================================
__global__ __launch_bounds__(256, 2)
void gemm_zx(const float* __restrict__ x,
             const float* __restrict__ Wf, const float* __restrict__ bf,
             const float* __restrict__ Wi, const float* __restrict__ bi,
             const float* __restrict__ Wo, const float* __restrict__ bo,
             const float* __restrict__ Wc, const float* __restrict__ bc)
{
    __shared__ float As[16 * 128];   // [k][m]
    __shared__ float Bs[16 * 128];   // [k][n]

    const int t = threadIdx.x;

    const float* Wg[4] = {Wf, Wi, Wo, Wc};
    const float* bg[4] = {bf, bi, bo, bc};

    const int N0 = blockIdx.x * 128;          // never straddles a gate
    const int gate = N0 >> 8;
    const int jb = N0 & 255;
    const float* __restrict__ W = Wg[gate];

    const int M0 = blockIdx.y * 128;
    const int tx = t & 15;
    const int ty = t >> 4;

    float acc[8][8];
    #pragma unroll
    for (int i = 0; i < 8; i++)
        #pragma unroll
        for (int j = 0; j < 8; j++) acc[i][j] = 0.f;

    for (int k0 = 0; k0 < 256; k0 += 16) {
        #pragma unroll
        for (int i = 0; i < 2; i++) {
            int f = t + i * 256;
            int kq  = f >> 7;
            int row = f & 127;
            int m   = M0 + row;
            int bb  = m & 31;
            int tt  = m >> 5;
            float4 a = *reinterpret_cast<const float4*>(
                x + ((size_t)bb * T_STEPS + tt) * 256 + k0 + kq * 4);
            As[(kq * 4 + 0) * 128 + row] = a.x;
            As[(kq * 4 + 1) * 128 + row] = a.y;
            As[(kq * 4 + 2) * 128 + row] = a.z;
            As[(kq * 4 + 3) * 128 + row] = a.w;
            int kk = f >> 5;
            int nq = f & 31;
            *reinterpret_cast<float4*>(&Bs[kk * 128 + nq * 4]) =
                *reinterpret_cast<const float4*>(W + (size_t)(k0 + kk) * 256 + jb + nq * 4);
        }
        __syncthreads();

        #pragma unroll
        for (int k = 0; k < 16; k++) {
            float a[8], bv[8];
            *reinterpret_cast<float4*>(&a[0])  = *reinterpret_cast<float4*>(&As[k * 128 + ty * 8]);
            *reinterpret_cast<float4*>(&a[4])  = *reinterpret_cast<float4*>(&As[k * 128 + ty * 8 + 4]);
            *reinterpret_cast<float4*>(&bv[0]) = *reinterpret_cast<float4*>(&Bs[k * 128 + tx * 8]);
            *reinterpret_cast<float4*>(&bv[4]) = *reinterpret_cast<float4*>(&Bs[k * 128 + tx * 8 + 4]);
            #pragma unroll
            for (int i = 0; i < 8; i++)
                #pragma unroll
                for (int j = 0; j < 8; j++)
                    acc[i][j] = fmaf(a[i], bv[j], acc[i][j]);
        }
        __syncthreads();
    }

    const float* __restrict__ bias = bg[gate];
    #pragma unroll
    for (int i = 0; i < 8; i++) {
        int m = M0 + ty * 8 + i;
        float* zr = g_Zx + (size_t)m * ZCOLS + N0 + tx * 8;
        float4 v0, v1;
        v0.x = acc[i][0] + bias[jb + tx * 8 + 0];
        v0.y = acc[i][1] + bias[jb + tx * 8 + 1];
        v0.z = acc[i][2] + bias[jb + tx * 8 + 2];
        v0.w = acc[i][3] + bias[jb + tx * 8 + 3];
        v1.x = acc[i][4] + bias[jb + tx * 8 + 4];
        v1.y = acc[i][5] + bias[jb + tx * 8 + 5];
        v1.z = acc[i][6] + bias[jb + tx * 8 + 6];
        v1.w = acc[i][7] + bias[jb + tx * 8 + 7];
        *reinterpret_cast<float4*>(zr)     = v0;
        *reinterpret_cast<float4*>(zr + 4) = v1;
    }
}

// ============================================================================
// Kernel 2: cluster recurrence; register weights, FFMA2, per-source slice
// mbarriers, st.async exchange (proven R9), PLUS:
//  - producer/consumer named barrier: GEMV warps 2-7 bar.arrive and skip tail
//  - unit-major s_part: GEMV thread owns 4 GATES of one unit -> tail combine
//    is 8x LDS.128 + packed f32x2 adds instead of 32 scalar LDS.
// ============================================================================
__device__ __forceinline__ uint32_t smem_u32(const void* p) {
    uint32_t a;
    asm("{ .reg .u64 t; cvta.to.shared.u64 t, %1; cvt.u32.u64 %0, t; }"
        : "=r"(a) : "l"(p));
    return a;
}

__device__ __forceinline__ float fast_sigmoid(float z) {
    return __fdividef(1.f, 1.f + __expf(-z));
}
__device__ __forceinline__ float fast_tanh(float z) {
    return 1.f - __fdividef(2.f, __expf(2.f * z) + 1.f);
}

#define FMA2(d, a, b) \
    asm("fma.rn.f32x2 %0, %1, %2, %3;" : "=l"(d) : "l"(a), "l"(b), "l"(d))
#define ADD2(d, a, b) \
    asm("add.rn.f32x2 %0, %1, %2;" : "=l"(d) : "l"(a), "l"(b))

__device__ __forceinline__ unsigned long long pack_f2(float lo, float hi) {
    float2 f = make_float2(lo, hi);
    return *reinterpret_cast<unsigned long long*>(&f);
}
__device__ __forceinline__ float unpack_sum(unsigned long long v) {
    float2 f = *reinterpret_cast<float2*>(&v);
    return f.x + f.y;
}
__device__ __forceinline__ float2 unpack2(unsigned long long v) {
    return *reinterpret_cast<float2*>(&v);
}

// smem layout: 16 mbarriers (128B), then floats
#define NBARS       16                   // 8 src x 2 (ping-pong)
#define SLICE_TX    256                  // bytes per (src, boundary)
#define SW_FLOATS   (256 * 128)          // weights [k][pc] (staging only)
#define SH_FLOATS   (2 * 2 * 256)        // h [buf][b][k]  (written by st.async)
#define SP_FLOATS   (8 * 2 * 128)        // partials [ks][b][unit*4+gate], x2
#define SC_FLOATS   (2 * 32)             // cell state [b][u]
#define SMEM_FLOATS (SW_FLOATS + SH_FLOATS + 2 * SP_FLOATS + SC_FLOATS)
#define SMEM_BYTES  (NBARS * 8 + SMEM_FLOATS * 4)

__global__ __launch_bounds__(REC_THREADS, 1) __cluster_dims__(CLUSTER, 1, 1)
void lstm_rec(const float* __restrict__ Wf, const float* __restrict__ Wi,
              const float* __restrict__ Wo, const float* __restrict__ Wc,
              float* __restrict__ out)
{
    extern __shared__ float smem_raw[];
    float* s_W    = smem_raw + NBARS * 2;     // [256][128] (staging)
    float* s_h    = s_W + SW_FLOATS;          // [2][2][256]
    float* s_part = s_h + SH_FLOATS;          // [2][8][2][32 units][4 gates]
    float* s_c    = s_part + 2 * SP_FLOATS;   // [2][32]

    const int tid  = threadIdx.x;
    const int rank = blockIdx.x & (CLUSTER - 1);
    const int cid  = blockIdx.x >> 3;
    const int bb0  = cid * 2;
    const float* Wg[4] = {Wf, Wi, Wo, Wc};

    const uint32_t smem_base = smem_u32(smem_raw);
    const uint32_t sh_base = smem_base + NBARS * 8 + SW_FLOATS * 4;
    #define BAR_ADDR(src, pp) (smem_base + (uint32_t)(((src) * 2 + (pp)) * 8))

    // stage weights once: s_W[k][pc] = Wg[pc>>5][(256+k)*256 + rank*32 + (pc&31)]
    for (int idx = tid; idx < SW_FLOATS; idx += REC_THREADS) {
        int k = idx >> 7, pc = idx & 127;
        s_W[idx] = Wg[pc >> 5][(size_t)(256 + k) * 256 + rank * 32 + (pc & 31)];
    }
    for (int i = tid; i < SH_FLOATS; i += REC_THREADS) s_h[i] = 0.f;
    if (tid < 64) s_c[tid] = 0.f;

    if (tid == 0) {
        #pragma unroll
        for (int i = 0; i < NBARS; i++) {
            uint32_t b = smem_base + (uint32_t)(i * 8);
            asm volatile("mbarrier.init.shared.b64 [%0], 1;" :: "r"(b) : "memory");
            asm volatile("mbarrier.arrive.expect_tx.shared.b64 _, [%0], %1;"
                         :: "r"(b), "r"(SLICE_TX) : "memory");
        }
    }
    __syncthreads();

    // GEMV roles: warp ks (32 k's = src ks's slice), lane colq = UNIT 0..31
    const int ks   = tid >> 5;
    const int colq = tid & 31;
    const int lane = tid & 31;

    // hoist 128 weights to regs, packed over k-parity; col c = gate c of unit
    // colq: pc = c*32 + colq
    unsigned long long wreg[4][16];
    #pragma unroll
    for (int c = 0; c < 4; c++)
        #pragma unroll
        for (int p = 0; p < 16; p++)
            wreg[c][p] = pack_f2(
                s_W[(ks * 32 + 2 * p)     * 128 + c * 32 + colq],
                s_W[(ks * 32 + 2 * p + 1) * 128 + c * 32 + colq]);

    asm volatile("barrier.cluster.arrive.aligned;" ::: "memory");
    asm volatile("barrier.cluster.wait.aligned;" ::: "memory");

    // tail roles (tid < 64): tb = batch, tu = unit
    const int tb = tid >> 5;
    const int tu = tid & 31;

    // per-warp barrier phase state
    int par0 = 0, par1 = 0;

    // Zx prefetch (tail threads): gates f,i,o,c for (tb, tu)
    float pf[4];
    if (tid < 64) {
        const float* z = g_Zx + ((size_t)0 * 32 + bb0 + tb) * ZCOLS + rank * 32 + tu;
        #pragma unroll
        for (int g = 0; g < 4; g++) pf[g] = __ldcg(z + g * 256);
    }

    for (int t = 0; t < T_STEPS; t++) {
        const int cbuf = t & 1, nbuf = cbuf ^ 1;

        // wait for THIS warp's slice (boundary t), t >= 1
        if (t >= 1) {
            const uint32_t bar = BAR_ADDR(ks, t & 1);
            const int par = (t & 1) ? par1 : par0;
            uint32_t done = 0;
            do {
                asm volatile(
                    "{\n\t.reg .pred p;\n\t"
                    "mbarrier.try_wait.parity.acquire.cta.shared::cta.b64 "
                    "p, [%1], %2, 0x989680;\n\t"
                    "selp.b32 %0, 1, 0, p;\n\t}"
                    : "=r"(done) : "r"(bar), "r"(par) : "memory");
            } while (!done);
            if (t & 1) par1 ^= 1; else par0 ^= 1;
            if (lane == 0 && t + 2 < T_STEPS) {
                asm volatile("mbarrier.arrive.expect_tx.shared.b64 _, [%0], %1;"
                             :: "r"(bar), "r"(SLICE_TX) : "memory");
            }
        }

        // GEMV: 4 gates x 2 batches x 32 k; reg weights, FFMA2
        {
            const float* hb0 = s_h + (cbuf * 2) * 256 + ks * 32;
            const float* hb1 = hb0 + 256;
            unsigned long long acc[4][2];
            #pragma unroll
            for (int c = 0; c < 4; c++) { acc[c][0] = 0ull; acc[c][1] = 0ull; }

            #pragma unroll
            for (int j = 0; j < 8; j++) {
                ulonglong2 H0 = *reinterpret_cast<const ulonglong2*>(hb0 + j * 4);
                ulonglong2 H1 = *reinterpret_cast<const ulonglong2*>(hb1 + j * 4);
                #pragma unroll
                for (int c = 0; c < 4; c++) {
                    FMA2(acc[c][0], wreg[c][2 * j],     H0.x);
                    FMA2(acc[c][0], wreg[c][2 * j + 1], H0.y);
                    FMA2(acc[c][1], wreg[c][2 * j],     H1.x);
                    FMA2(acc[c][1], wreg[c][2 * j + 1], H1.y);
                }
            }
            // unit-major store: float4 = (f,i,o,c) partials of unit colq
            float* pw = s_part + cbuf * SP_FLOATS + (ks * 2) * 128 + colq * 4;
            float4 A0, A1;
            A0.x = unpack_sum(acc[0][0]); A0.y = unpack_sum(acc[1][0]);
            A0.z = unpack_sum(acc[2][0]); A0.w = unpack_sum(acc[3][0]);
            A1.x = unpack_sum(acc[0][1]); A1.y = unpack_sum(acc[1][1]);
            A1.z = unpack_sum(acc[2][1]); A1.w = unpack_sum(acc[3][1]);
            *reinterpret_cast<float4*>(pw)       = A0;
            *reinterpret_cast<float4*>(pw + 128) = A1;
        }

        // producer/consumer barrier: GEMV warps arrive and move on; tail waits
        if (tid < 64) {
            asm volatile("bar.sync 1, %0;" :: "r"(REC_THREADS) : "memory");

            // fused tail: combine (8x LDS.128 + f32x2 adds) + gates + c,h
            unsigned long long zlo = pack_f2(pf[0], pf[1]);   // (f, i)
            unsigned long long zhi = pack_f2(pf[2], pf[3]);   // (o, c)
            const float* pb = s_part + cbuf * SP_FLOATS + tb * 128 + tu * 4;
            #pragma unroll
            for (int q = 0; q < 8; q++) {
                ulonglong2 v = *reinterpret_cast<const ulonglong2*>(pb + q * 256);
                ADD2(zlo, zlo, v.x);
                ADD2(zhi, zhi, v.y);
            }
            float2 zfi = unpack2(zlo);
            float2 zoc = unpack2(zhi);
            float fg = fast_sigmoid(zfi.x);
            float ig = fast_sigmoid(zfi.y);
            float og = fast_sigmoid(zoc.x);
            float gg = fast_tanh(zoc.y);
            float cv = fmaf(fg, s_c[tid], ig * gg);
            s_c[tid] = cv;
            float hv = og * fast_tanh(cv);

            // push FIRST (unblocks peers): lane-paired 8B st.async to 8 ranks
            if (t + 1 < T_STEPS) {
                float hp = __shfl_xor_sync(0xffffffffu, hv, 1);
                if ((tu & 1) == 0) {
                    double val;
                    {
                        float2 f2 = make_float2(hv, hp);
                        val = *reinterpret_cast<double*>(&f2);
                    }
                    uint32_t daddr = sh_base
                        + (uint32_t)(((nbuf * 2 + tb) * 256 + rank * 32 + tu) * 4);
                    uint32_t baddr = BAR_ADDR(rank, (t + 1) & 1);
                    #pragma unroll
                    for (int p = 0; p < CLUSTER; p++) {
                        asm volatile(
                            "{\n\t.reg .b32 ra, rb;\n\t"
                            "mapa.shared::cluster.u32 ra, %0, %2;\n\t"
                            "mapa.shared::cluster.u32 rb, %1, %2;\n\t"
                            "st.async.shared::cluster.mbarrier::complete_tx::bytes.b64 "
                            "[ra], %3, [rb];\n\t}"
                            :: "r"(daddr), "r"(baddr), "r"(p), "d"(val) : "memory");
                    }
                }
            }

            // output (fire-and-forget)
            out[((size_t)(bb0 + tb) * T_STEPS + (T_STEPS - 1 - t)) * HID
                + rank * 32 + tu] = hv;

            // prefetch Zx(t+1)
            if (t + 1 < T_STEPS) {
                const float* z = g_Zx + ((size_t)(t + 1) * 32 + bb0 + tb) * ZCOLS
                               + rank * 32 + tu;
                #pragma unroll
                for (int g = 0; g < 4; g++) pf[g] = __ldcg(z + g * 256);
            }
        } else {
            // non-tail warps: arrive (non-blocking) and go poll next slice.
            // Phase-safe: their t+1 GEMV is gated on slices that transitively
            // require this CTA's tail of step t, which requires this trip.
            asm volatile("bar.arrive 1, %0;" :: "r"(REC_THREADS) : "memory");
        }
    }

    // DSMEM discipline: no CTA exits while peers could still target it
    asm volatile("barrier.cluster.arrive.aligned;" ::: "memory");
    asm volatile("barrier.cluster.wait.aligned;" ::: "memory");
}

// ============================================================================
extern "C" void kernel_launch(void* const* d_in, const int* in_sizes, int n_in,
                              void* d_out, int out_size)
{
    const float* x  = (const float*)d_in[0];
    const float* Wf = (const float*)d_in[1];
    const float* bf = (const float*)d_in[2];
    const float* Wi = (const float*)d_in[3];
    const float* bi = (const float*)d_in[4];
    const float* Wo = (const float*)d_in[5];
    const float* bo = (const float*)d_in[6];
    const float* Wc = (const float*)d_in[7];
    const float* bc = (const float*)d_in[8];
    float* out = (float*)d_out;

    cudaFuncSetAttribute(lstm_rec,
                         cudaFuncAttributeMaxDynamicSharedMemorySize, SMEM_BYTES);

    dim3 g1(ZCOLS / 128, MROWS / 128);   // 8 x 512
    gemm_zx<<<g1, 256>>>(x, Wf, bf, Wi, bi, Wo, bo, Wc, bc);
    lstm_rec<<<REC_CTAS, REC_THREADS, SMEM_BYTES>>>(Wf, Wi, Wo, Wc, out);
}